// round 8
// baseline (speedup 1.0000x reference)
#include <cuda_runtime.h>
#include <cuda_bf16.h>
#include <cstdint>

// AddingGaussianBlur: x (64,512,512,3) f32, stds (64,) f32 -> out f32.
//
// Separable (reference's 3x3 kernel depends only on column index):
//   vertical  : unweighted 3-row sum (zero padded)
//   horizontal: [a, 1, a] / (3*(1+2a)),  a = exp(-1/s^2), s = 3*std[b]
//
// R8 = R7 (cp.async row ring, thread-private; register vertical window; smem
// vsum exchange) +
//   - cp.async.cg: input bypasses L1 (read-once data) -> L1 pressure down
//   - 2 rows per iteration: barriers and wait_groups halved
//   - 4 rows in flight (2 groups x 2 rows pending)

#define H       512
#define ROWW    1536            // 512 * 3 floats per image row
#define NT      384             // 384 threads x float4 = one row
#define RPB     32              // rows per block band
#define NSLOT   4               // ring slots
#define PAD     4               // float halo each side of vsum row
#define SROW    (ROWW + 2 * PAD)

__global__ __launch_bounds__(NT)
void gauss_blur_kernel(const float* __restrict__ x,
                       const float* __restrict__ stds,
                       float* __restrict__ out)
{
    __shared__ __align__(16) float ring[NSLOT][ROWW];
    __shared__ __align__(16) float vs[4][SROW];

    const int b  = blockIdx.y;
    const int i0 = blockIdx.x * RPB;
    const int t  = threadIdx.x;

    // zero vsum halos of all 4 buffers once (visible after first barrier)
    if (t < 16) {
        const int buf = t >> 2, idx = t & 3;
        vs[buf][idx] = 0.0f;
        vs[buf][ROWW + PAD + idx] = 0.0f;
    }

    const float s   = stds[b] * 3.0f;
    const float a   = expf(-1.0f / (s * s));
    const float inv = 1.0f / (3.0f * (1.0f + 2.0f * a));

    const float* __restrict__ xb = x   + (size_t)b * H * ROWW;
    float*       __restrict__ ob = out + (size_t)b * H * ROWW;

    const uint32_t ring_smem = (uint32_t)__cvta_generic_to_shared(&ring[0][0]) + t * 16u;
    const float4 Z = make_float4(0.0f, 0.0f, 0.0f, 0.0f);

    // Issue one row into the ring (cp.async.cg if in range, STS zeros
    // otherwise). Always commits a group so wait_group counts stay static.
    auto issue = [&](int gi) {
        const int slot = (gi - i0 + 1) & (NSLOT - 1);
        if ((unsigned)gi < (unsigned)H) {
            const float* src = xb + (size_t)gi * ROWW + t * 4;
            const uint32_t dst = ring_smem + slot * (ROWW * 4);
            asm volatile("cp.async.cg.shared.global [%0], [%1], 16;\n"
                         :: "r"(dst), "l"(src));
        } else {
            reinterpret_cast<float4*>(ring[slot] + t * 4)[0] = Z;
        }
        asm volatile("cp.async.commit_group;\n");
    };

    // Prologue: rows i0-1 .. i0+2 (4 groups), drain to 2 pending so rows
    // i0-1, i0 are resident.
    issue(i0 - 1);
    issue(i0);
    issue(i0 + 1);
    issue(i0 + 2);
    asm volatile("cp.async.wait_group 2;\n");

    float4 rm = reinterpret_cast<const float4*>(ring[0] + t * 4)[0];  // row i0-1
    float4 rc = reinterpret_cast<const float4*>(ring[1] + t * 4)[0];  // row i0

    int par = 0;
    #pragma unroll 1
    for (int r = 0; r < RPB; r += 2) {
        const int gi = i0 + r;

        // keep 4 rows in flight: issue gi+3, gi+4
        issue(gi + 3);
        issue(gi + 4);
        // rows <= gi+2 complete (pending: gi+3, gi+4)
        asm volatile("cp.async.wait_group 2;\n");

        const float4 rp = reinterpret_cast<const float4*>(
                              ring[(r + 2) & (NSLOT - 1)] + t * 4)[0];  // gi+1
        const float4 rq = reinterpret_cast<const float4*>(
                              ring[(r + 3) & (NSLOT - 1)] + t * 4)[0];  // gi+2

        // vertical sums for output rows gi and gi+1
        float4 v0, v1;
        v0.x = rm.x + rc.x + rp.x;  v1.x = rc.x + rp.x + rq.x;
        v0.y = rm.y + rc.y + rp.y;  v1.y = rc.y + rp.y + rq.y;
        v0.z = rm.z + rc.z + rp.z;  v1.z = rc.z + rp.z + rq.z;
        v0.w = rm.w + rc.w + rp.w;  v1.w = rc.w + rp.w + rq.w;

        float* s0 = vs[par * 2];
        float* s1 = vs[par * 2 + 1];
        reinterpret_cast<float4*>(s0 + PAD)[t] = v0;
        reinterpret_cast<float4*>(s1 + PAD)[t] = v1;
        __syncthreads();

        // neighbor chunks (16B aligned): L = vsum[4t-4..4t-1], R = vsum[4t+4..4t+7]
        const float4 L0 = reinterpret_cast<const float4*>(s0)[t];
        const float4 R0 = reinterpret_cast<const float4*>(s0 + PAD + 4)[t];
        const float4 L1 = reinterpret_cast<const float4*>(s1)[t];
        const float4 R1 = reinterpret_cast<const float4*>(s1 + PAD + 4)[t];

        // out[e] = inv * (a*(vsum[e-3] + vsum[e+3]) + vsum[e]),  e = 4t+j
        float4 o0, o1;
        o0.x = inv * (a * (L0.y + v0.w) + v0.x);
        o0.y = inv * (a * (L0.z + R0.x) + v0.y);
        o0.z = inv * (a * (L0.w + R0.y) + v0.z);
        o0.w = inv * (a * (v0.x + R0.z) + v0.w);

        o1.x = inv * (a * (L1.y + v1.w) + v1.x);
        o1.y = inv * (a * (L1.z + R1.x) + v1.y);
        o1.z = inv * (a * (L1.w + R1.y) + v1.z);
        o1.w = inv * (a * (v1.x + R1.z) + v1.w);

        __stcs(&reinterpret_cast<float4*>(ob + (size_t)gi       * ROWW)[t], o0);
        __stcs(&reinterpret_cast<float4*>(ob + (size_t)(gi + 1) * ROWW)[t], o1);

        // rotate window by 2 rows; flip vsum buffer pair (reuse is two
        // iterations away, ordered by the intervening __syncthreads)
        rm = rp; rc = rq;
        par ^= 1;
    }
}

extern "C" void kernel_launch(void* const* d_in, const int* in_sizes, int n_in,
                              void* d_out, int out_size)
{
    const float* x    = (const float*)d_in[0];
    const float* stds = (const float*)d_in[1];
    float* out        = (float*)d_out;

    dim3 grid(H / RPB, 64);   // (16, 64) = 1024 blocks
    gauss_blur_kernel<<<grid, NT>>>(x, stds, out);
}